// round 15
// baseline (speedup 1.0000x reference)
#include <cuda_runtime.h>
#include <cuda_fp16.h>
#include <cstdint>
#include <cstddef>

typedef __half f16;
#define DI __device__ __forceinline__

constexpr int Bn = 4, Pn = 1024, Xn = 8192, Cn = 1024;
// symmetric fold: q *= S32, k *= c * S32  ->  q.k carries 1/32 = 1/sqrt(C)
#define S32 0.1767766952966369f

// ---------------- scratch (device globals, no allocation) ----------------
__device__ f16   g_qh[(size_t)Bn * Pn * Cn];
__device__ f16   g_ql[(size_t)Bn * Pn * Cn];   // only read by repair
__device__ f16   g_kh[(size_t)Bn * Xn * Cn];
__device__ f16   g_kl[(size_t)Bn * Xn * Cn];   // only read by repair
__device__ f16   g_v [(size_t)Bn * Xn * Cn];
__device__ float g_S [(size_t)Bn * Pn * Xn];   // scores fp32

// ---------------- PTX helpers ----------------
DI void cp_async16(uint32_t saddr, const void* gptr) {
    asm volatile("cp.async.cg.shared.global [%0], [%1], 16;\n" :: "r"(saddr), "l"(gptr));
}
DI void cp_commit() { asm volatile("cp.async.commit_group;\n"); }
template <int N> DI void cp_wait() { asm volatile("cp.async.wait_group %0;\n" :: "n"(N)); }

DI void ldsm4(uint32_t addr, uint32_t& r0, uint32_t& r1, uint32_t& r2, uint32_t& r3) {
    asm volatile("ldmatrix.sync.aligned.m8n8.x4.shared.b16 {%0,%1,%2,%3}, [%4];\n"
                 : "=r"(r0), "=r"(r1), "=r"(r2), "=r"(r3) : "r"(addr));
}
DI void mma16816(float c[4], const uint32_t a[4], const uint32_t b[2]) {
    asm volatile(
        "mma.sync.aligned.m16n8k16.row.col.f32.f16.f16.f32 "
        "{%0,%1,%2,%3}, {%4,%5,%6,%7}, {%8,%9}, {%0,%1,%2,%3};\n"
        : "+f"(c[0]), "+f"(c[1]), "+f"(c[2]), "+f"(c[3])
        : "r"(a[0]), "r"(a[1]), "r"(a[2]), "r"(a[3]), "r"(b[0]), "r"(b[1]));
}

// Swizzled byte offset inside a 128-row x 64-col f16 tile (128B rows, SW128 XOR).
DI uint32_t swz(int r, int c8) { return (uint32_t)(r * 128 + ((c8 ^ (r & 7)) << 4)); }

// ---------------- LayerNorm -> f16 (optionally hi/lo split), C = 1024 ----------------
__global__ void __launch_bounds__(256) ln_kernel(
    const float* __restrict__ src, f16* __restrict__ dst_h, f16* __restrict__ dst_l,
    const float* __restrict__ gamma, const float* __restrict__ beta,
    const float* __restrict__ cscale, float sconst)
{
    const int row = blockIdx.x;
    const int t = threadIdx.x;
    const float4* s4 = reinterpret_cast<const float4*>(src) + (size_t)row * 256;
    float4 x = s4[t];
    float sum = x.x + x.y + x.z + x.w;
    float sq  = fmaf(x.x, x.x, fmaf(x.y, x.y, fmaf(x.z, x.z, x.w * x.w)));
#pragma unroll
    for (int o = 16; o; o >>= 1) {
        sum += __shfl_xor_sync(0xffffffffu, sum, o);
        sq  += __shfl_xor_sync(0xffffffffu, sq,  o);
    }
    __shared__ float s_sum[8], s_sq[8];
    if ((t & 31) == 0) { s_sum[t >> 5] = sum; s_sq[t >> 5] = sq; }
    __syncthreads();
    sum = 0.f; sq = 0.f;
#pragma unroll
    for (int i = 0; i < 8; i++) { sum += s_sum[i]; sq += s_sq[i]; }
    const float mu  = sum * (1.f / 1024.f);
    const float var = sq * (1.f / 1024.f) - mu * mu;
    const float rs  = rsqrtf(var + 1e-5f);
    const float sc  = (cscale ? __ldg(cscale + row) : 1.f) * sconst;

    const float4 g = reinterpret_cast<const float4*>(gamma)[t];
    const float4 b = reinterpret_cast<const float4*>(beta)[t];
    float y[4];
    y[0] = ((x.x - mu) * rs * g.x + b.x) * sc;
    y[1] = ((x.y - mu) * rs * g.y + b.y) * sc;
    y[2] = ((x.z - mu) * rs * g.z + b.z) * sc;
    y[3] = ((x.w - mu) * rs * g.w + b.w) * sc;

    __half2 h01 = __floats2half2_rn(y[0], y[1]);
    __half2 h23 = __floats2half2_rn(y[2], y[3]);
    uint2 pk;
    pk.x = *reinterpret_cast<uint32_t*>(&h01);
    pk.y = *reinterpret_cast<uint32_t*>(&h23);
    reinterpret_cast<uint2*>(dst_h + (size_t)row * 1024)[t] = pk;

    if (dst_l) {
        float l0 = y[0] - __half2float(__low2half(h01));
        float l1 = y[1] - __half2float(__high2half(h01));
        float l2 = y[2] - __half2float(__low2half(h23));
        float l3 = y[3] - __half2float(__high2half(h23));
        __half2 l01 = __floats2half2_rn(l0, l1);
        __half2 l23 = __floats2half2_rn(l2, l3);
        uint2 pl;
        pl.x = *reinterpret_cast<uint32_t*>(&l01);
        pl.y = *reinterpret_cast<uint32_t*>(&l23);
        reinterpret_cast<uint2*>(dst_l + (size_t)row * 1024)[t] = pl;
    }
}

// ---------------- tiled f16 GEMM (GEMM1 only): 128x128 CTA tile, fp32 out ----------
// Pointers are pre-offset per batch; grid is (N/128, M/128, 1).
template <int STAGES>
__global__ void __launch_bounds__(256, 2) gemm_kernel(
    const f16* __restrict__ A0, const f16* __restrict__ B0,
    float* __restrict__ Co, int M, int N, int K)
{
    extern __shared__ __align__(1024) char smem_raw[];
    constexpr int TILE = 16384;                       // 128x64 f16
    constexpr int SS   = 2 * TILE;
    const int tid = threadIdx.x, lane = tid & 31, warp = tid >> 5;
    const int wm = warp & 3, wn = warp >> 2;          // 4 x 2 warp grid
    const int bN = blockIdx.x, bM = blockIdx.y;

    const f16* Ap = A0 + (size_t)bM * 128 * K;
    const f16* Bp = B0 + (size_t)bN * 128 * K;

    const uint32_t sb = (uint32_t)__cvta_generic_to_shared(smem_raw);
    const int KT = K >> 6;

    auto fill = [&](int t) {
        const int k0 = t * 64;
        const uint32_t base = sb + (uint32_t)(t % STAGES) * SS;
#pragma unroll
        for (int i = 0; i < 4; i++) {
            int idx = tid + i * 256; int r = idx >> 3, c8 = idx & 7;
            cp_async16(base + swz(r, c8), Ap + (size_t)r * K + k0 + c8 * 8);
        }
#pragma unroll
        for (int i = 0; i < 4; i++) {
            int idx = tid + i * 256; int r = idx >> 3, c8 = idx & 7;
            cp_async16(base + TILE + swz(r, c8), Bp + (size_t)r * K + k0 + c8 * 8);
        }
        cp_commit();
    };

    float acc[2][8][4];
#pragma unroll
    for (int mt = 0; mt < 2; mt++)
#pragma unroll
        for (int nt = 0; nt < 8; nt++)
#pragma unroll
            for (int i = 0; i < 4; i++) acc[mt][nt][i] = 0.f;

#pragma unroll
    for (int t = 0; t < STAGES - 1; t++) fill(t);

    for (int kt = 0; kt < KT; kt++) {
        cp_wait<STAGES - 2>();
        __syncthreads();
        { const int t = kt + STAGES - 1; if (t < KT) fill(t); else cp_commit(); }

        const uint32_t base = sb + (uint32_t)(kt % STAGES) * SS;
        const uint32_t sA = base;
        const uint32_t sB = base + TILE;
#pragma unroll
        for (int kk = 0; kk < 4; kk++) {
            uint32_t bh[8][2];
#pragma unroll
            for (int np = 0; np < 4; np++) {
                int r = wn * 64 + np * 16 + ((lane >> 4) << 3) + (lane & 7);
                int c8 = kk * 2 + ((lane >> 3) & 1);
                ldsm4(sB + swz(r, c8), bh[2 * np][0], bh[2 * np][1],
                                        bh[2 * np + 1][0], bh[2 * np + 1][1]);
            }
            uint32_t ah[2][4];
#pragma unroll
            for (int mt = 0; mt < 2; mt++) {
                int r = wm * 32 + mt * 16 + (lane & 15);
                int c8 = kk * 2 + (lane >> 4);
                ldsm4(sA + swz(r, c8), ah[mt][0], ah[mt][1], ah[mt][2], ah[mt][3]);
            }
#pragma unroll
            for (int mt = 0; mt < 2; mt++)
#pragma unroll
                for (int nt = 0; nt < 8; nt++)
                    mma16816(acc[mt][nt], ah[mt], bh[nt]);
        }
    }

    const int row0 = bM * 128 + wm * 32;
    const int col0 = bN * 128 + wn * 64;
    const int tr = lane >> 2, tc = (lane & 3) << 1;
#pragma unroll
    for (int mt = 0; mt < 2; mt++)
#pragma unroll
        for (int nt = 0; nt < 8; nt++) {
            int p = row0 + mt * 16 + tr, x = col0 + nt * 8 + tc;
            *reinterpret_cast<float2*>(Co + (size_t)p * N + x) =
                make_float2(acc[mt][nt][0], acc[mt][nt][1]);
            *reinterpret_cast<float2*>(Co + (size_t)(p + 8) * N + x) =
                make_float2(acc[mt][nt][2], acc[mt][nt][3]);
        }
}

// ---------------- fused softmax + repair + sparse SpMM + residual ----------------
DI float blockMax(float v, float* red) {
#pragma unroll
    for (int o = 16; o; o >>= 1) v = fmaxf(v, __shfl_xor_sync(0xffffffffu, v, o));
    __syncthreads();
    if ((threadIdx.x & 31) == 0) red[threadIdx.x >> 5] = v;
    __syncthreads();
    float r = red[0];
#pragma unroll
    for (int i = 1; i < 8; i++) r = fmaxf(r, red[i]);
    return r;
}
DI float blockSum(float v, float* red) {
#pragma unroll
    for (int o = 16; o; o >>= 1) v += __shfl_xor_sync(0xffffffffu, v, o);
    __syncthreads();
    if ((threadIdx.x & 31) == 0) red[threadIdx.x >> 5] = v;
    __syncthreads();
    float r = 0.f;
#pragma unroll
    for (int i = 0; i < 8; i++) r += red[i];
    return r;
}

constexpr int FCAP = 1024;

// All pointers are BASE pointers; addressing uses the global row = row_base + blockIdx.x.
__global__ void __launch_bounds__(256) softmax_spmm_kernel(
    const float* __restrict__ S,
    const f16* __restrict__ qh, const f16* __restrict__ ql,
    const f16* __restrict__ kh, const f16* __restrict__ kl,
    const f16* __restrict__ V, const float* __restrict__ feat,
    float* __restrict__ out, int row_base)
{
    __shared__ float red[8];
    __shared__ float q_s[1024];
    __shared__ int   nf;
    __shared__ int   fx[FCAP];
    __shared__ float fsn[FCAP];
    __shared__ int   sidx[1024];
    __shared__ float sval[1024];
    __shared__ int   wtot[8], wbase[8], s_total;

    const int row = row_base + blockIdx.x;     // global row: b*Pn + p
    const int bz  = row >> 10;                 // Pn = 1024
    const int t = threadIdx.x;
    const int lane = t & 31, warp = t >> 5;

    // preload exact q row (qh+ql) to smem
    {
        const uint2 ph = reinterpret_cast<const uint2*>(qh + (size_t)row * 1024)[t];
        const uint2 pl = reinterpret_cast<const uint2*>(ql + (size_t)row * 1024)[t];
        __half2 h0 = *reinterpret_cast<const __half2*>(&ph.x);
        __half2 h1 = *reinterpret_cast<const __half2*>(&ph.y);
        __half2 l0 = *reinterpret_cast<const __half2*>(&pl.x);
        __half2 l1 = *reinterpret_cast<const __half2*>(&pl.y);
        q_s[4 * t + 0] = __low2float(h0)  + __low2float(l0);
        q_s[4 * t + 1] = __high2float(h0) + __high2float(l0);
        q_s[4 * t + 2] = __low2float(h1)  + __low2float(l1);
        q_s[4 * t + 3] = __high2float(h1) + __high2float(l1);
    }
    if (t == 0) nf = 0;

    // load fp32 scores: 8 x float4 = 32 values per thread
    const float4* s4 = reinterpret_cast<const float4*>(S + (size_t)row * Xn);
    float v[8][4];
    float m = -1e30f;
#pragma unroll
    for (int i = 0; i < 8; i++) {
        float4 vv = s4[t + i * 256];
        v[i][0] = vv.x; v[i][1] = vv.y; v[i][2] = vv.z; v[i][3] = vv.w;
        m = fmaxf(m, fmaxf(fmaxf(vv.x, vv.y), fmaxf(vv.z, vv.w)));
    }
    m = blockMax(m, red);                      // also fences q_s / nf writes

    // single exp pass: v becomes e = exp(s - m)
    float z = 0.f;
#pragma unroll
    for (int i = 0; i < 8; i++)
#pragma unroll
        for (int j = 0; j < 4; j++) { v[i][j] = __expf(v[i][j] - m); z += v[i][j]; }
    z = blockSum(z, red);

    // flag entries within +-2e-3 (log domain) of the approximate threshold
    const float ethr1 = 0.0005f * z;
    const float lo = ethr1 * 0.998002f;        // exp(-2e-3)
    const float hi = ethr1 * 1.002002f;        // exp(+2e-3)
#pragma unroll
    for (int i = 0; i < 8; i++)
#pragma unroll
        for (int j = 0; j < 4; j++) {
            if (v[i][j] > lo && v[i][j] < hi) {
                int sl = atomicAdd(&nf, 1);
                if (sl < FCAP) fx[sl] = 4 * (t + i * 256) + j;
            }
        }
    __syncthreads();
    const int nfc = min(nf, FCAP);

    // exact fp32 recompute of flagged scores: one warp per entry
    for (int e = warp; e < nfc; e += 8) {
        const int x = fx[e];
        const uint2* khp = reinterpret_cast<const uint2*>(kh + ((size_t)bz * Xn + x) * 1024);
        const uint2* klp = reinterpret_cast<const uint2*>(kl + ((size_t)bz * Xn + x) * 1024);
        float sum = 0.f;
#pragma unroll
        for (int jj = 0; jj < 8; jj++) {
            const int c4 = lane + jj * 32;
            const uint2 ph = khp[c4];
            const uint2 pl = klp[c4];
            __half2 h0 = *reinterpret_cast<const __half2*>(&ph.x);
            __half2 h1 = *reinterpret_cast<const __half2*>(&ph.y);
            __half2 l0 = *reinterpret_cast<const __half2*>(&pl.x);
            __half2 l1 = *reinterpret_cast<const __half2*>(&pl.y);
            sum = fmaf(q_s[4 * c4 + 0], __low2float(h0)  + __low2float(l0),  sum);
            sum = fmaf(q_s[4 * c4 + 1], __high2float(h0) + __high2float(l0), sum);
            sum = fmaf(q_s[4 * c4 + 2], __low2float(h1)  + __low2float(l1),  sum);
            sum = fmaf(q_s[4 * c4 + 3], __high2float(h1) + __high2float(l1), sum);
        }
#pragma unroll
        for (int o = 16; o; o >>= 1) sum += __shfl_xor_sync(0xffffffffu, sum, o);
        if (lane == 0) fsn[e] = __expf(sum - m);   // exact exp value
    }
    __syncthreads();

    // patch my registers with exact exp values
    for (int e = 0; e < nfc; e++) {
        const int x = fx[e];
        const int q4 = x >> 2;
        if ((q4 & 255) == t) v[q4 >> 8][x & 3] = fsn[e];
    }

    // rebuild Z and threshold from patched values (deterministic full reduction)
    float z_p = 0.f;
#pragma unroll
    for (int i = 0; i < 8; i++)
#pragma unroll
        for (int j = 0; j < 4; j++) z_p += v[i][j];
    z_p = blockSum(z_p, red);
    const float ethr = 0.0005f * z_p;

    float z2 = 0.f;
#pragma unroll
    for (int i = 0; i < 8; i++)
#pragma unroll
        for (int j = 0; j < 4; j++)
            if (v[i][j] >= ethr) z2 += v[i][j];
    z2 = blockSum(z2, red);
    const float inv = 1.f / z2;

    // ---- sparse SpMM: out = feat + inv * sum_{survivors} e_x * V[x, :] ----
    const f16* vb = V + (size_t)bz * Xn * 1024;
    float a0 = 0.f, a1 = 0.f, a2 = 0.f, a3 = 0.f;

    for (int i = 0; i < 8; i++) {
        // survivor mask among my 4 entries of this chunk
        int msk = 0;
#pragma unroll
        for (int j = 0; j < 4; j++) if (v[i][j] >= ethr) msk |= (1 << j);
        int cnt = __popc((unsigned)msk);

        // deterministic compaction: warp inclusive scan + block scan of warp totals
        unsigned inc = (unsigned)cnt;
#pragma unroll
        for (int o = 1; o < 32; o <<= 1) {
            unsigned xx = __shfl_up_sync(0xffffffffu, inc, o);
            if (lane >= o) inc += xx;
        }
        if (lane == 31) wtot[warp] = (int)inc;
        __syncthreads();
        if (t == 0) {
            int s = 0;
#pragma unroll
            for (int w = 0; w < 8; w++) { wbase[w] = s; s += wtot[w]; }
            s_total = s;
        }
        __syncthreads();
        int pos = wbase[warp] + (int)inc - cnt;
#pragma unroll
        for (int j = 0; j < 4; j++) {
            if (msk & (1 << j)) {
                sidx[pos] = 4 * (t + i * 256) + j;
                sval[pos] = v[i][j];
                pos++;
            }
        }
        __syncthreads();
        const int sc = s_total;

        // accumulate survivors: coalesced 2KB gathers of V rows (2-way unrolled for MLP)
        int e = 0;
        for (; e + 2 <= sc; e += 2) {
            const int x0 = sidx[e],     x1 = sidx[e + 1];
            const float w0 = sval[e],   w1 = sval[e + 1];
            const uint2 pv0 = *reinterpret_cast<const uint2*>(vb + (size_t)x0 * 1024 + 4 * t);
            const uint2 pv1 = *reinterpret_cast<const uint2*>(vb + (size_t)x1 * 1024 + 4 * t);
            __half2 a = *reinterpret_cast<const __half2*>(&pv0.x);
            __half2 b = *reinterpret_cast<const __half2*>(&pv0.y);
            __half2 c = *reinterpret_cast<const __half2*>(&pv1.x);
            __half2 d = *reinterpret_cast<const __half2*>(&pv1.y);
            float2 f0 = __half22float2(a), f1 = __half22float2(b);
            float2 f2 = __half22float2(c), f3 = __half22float2(d);
            a0 = fmaf(w0, f0.x, a0); a1 = fmaf(w0, f0.y, a1);
            a2 = fmaf(w0, f1.x, a2); a3 = fmaf(w0, f1.y, a3);
            a0 = fmaf(w1, f2.x, a0); a1 = fmaf(w1, f2.y, a1);
            a2 = fmaf(w1, f3.x, a2); a3 = fmaf(w1, f3.y, a3);
        }
        if (e < sc) {
            const int x = sidx[e];
            const float w = sval[e];
            const uint2 pv = *reinterpret_cast<const uint2*>(vb + (size_t)x * 1024 + 4 * t);
            __half2 a = *reinterpret_cast<const __half2*>(&pv.x);
            __half2 b = *reinterpret_cast<const __half2*>(&pv.y);
            float2 f0 = __half22float2(a), f1 = __half22float2(b);
            a0 = fmaf(w, f0.x, a0); a1 = fmaf(w, f0.y, a1);
            a2 = fmaf(w, f1.x, a2); a3 = fmaf(w, f1.y, a3);
        }
        __syncthreads();   // protect sidx/sval/wtot for next chunk
    }

    const float4 fr = *reinterpret_cast<const float4*>(feat + (size_t)row * 1024 + 4 * t);
    float4 o4;
    o4.x = fr.x + inv * a0;
    o4.y = fr.y + inv * a1;
    o4.z = fr.z + inv * a2;
    o4.w = fr.w + inv * a3;
    *reinterpret_cast<float4*>(out + (size_t)row * 1024 + 4 * t) = o4;
}

// ---------------- launch: GEMM1(b) on main ∥ fused(b) on side stream -------------
extern "C" void kernel_launch(void* const* d_in, const int* in_sizes, int n_in,
                              void* d_out, int out_size)
{
    const float* feat  = (const float*)d_in[0];
    const float* mem_k = (const float*)d_in[1];
    const float* mem_v = (const float*)d_in[2];
    const float* mem_c = (const float*)d_in[3];
    // d_in[4] = mem_attn (unused by reference)
    const float* gq = (const float*)d_in[5];
    const float* bq = (const float*)d_in[6];
    const float* gk = (const float*)d_in[7];
    const float* bk = (const float*)d_in[8];
    const float* gv = (const float*)d_in[9];
    const float* bv = (const float*)d_in[10];
    float* out = (float*)d_out;

    f16 *qh, *ql, *kh, *kl, *v;
    float* S;
    cudaGetSymbolAddress((void**)&qh, g_qh);
    cudaGetSymbolAddress((void**)&ql, g_ql);
    cudaGetSymbolAddress((void**)&kh, g_kh);
    cudaGetSymbolAddress((void**)&kl, g_kl);
    cudaGetSymbolAddress((void**)&v,  g_v);
    cudaGetSymbolAddress((void**)&S,  g_S);

    // side stream + events, created once on the first (non-capturing) call
    static cudaStream_t s2 = nullptr;
    static cudaEvent_t evFork = nullptr, evJoin = nullptr;
    static cudaEvent_t evG1[Bn] = {nullptr, nullptr, nullptr, nullptr};
    if (!s2) {
        cudaStreamCreateWithFlags(&s2, cudaStreamNonBlocking);
        cudaEventCreateWithFlags(&evFork, cudaEventDisableTiming);
        cudaEventCreateWithFlags(&evJoin, cudaEventDisableTiming);
        for (int b = 0; b < Bn; b++)
            cudaEventCreateWithFlags(&evG1[b], cudaEventDisableTiming);
    }

    // smem: 3 stages x 32KB = 98304 -> 2 CTAs/SM
    const int SM = 3 * 2 * 16384;
    cudaFuncSetAttribute(gemm_kernel<3>, cudaFuncAttributeMaxDynamicSharedMemorySize, SM);

    // fork: V-path (ln_v) on the side stream — needed only by the fused kernel
    cudaEventRecord(evFork, 0);
    cudaStreamWaitEvent(s2, evFork, 0);
    ln_kernel<<<Bn * Xn, 256, 0, s2>>>(mem_v, v, nullptr, gv, bv, nullptr, 1.f);

    // main path: LN for q and k
    ln_kernel<<<Bn * Pn, 256>>>(feat,  qh, ql, gq, bq, nullptr, S32);
    ln_kernel<<<Bn * Xn, 256>>>(mem_k, kh, kl, gk, bk, mem_c,   S32);

    // per-batch GEMM1 on main stream; fused(b) on side stream overlaps later GEMM1s.
    // Complementary profiles: GEMM1 is tensor-bound (L2 22%), fused is L2/latency-bound
    // (tensor 0%), so co-residency wastes neither pipe.
    for (int b = 0; b < Bn; b++) {
        gemm_kernel<3><<<dim3(Xn / 128, Pn / 128, 1), 256, SM>>>(
            qh + (size_t)b * Pn * Cn, kh + (size_t)b * Xn * Cn,
            S + (size_t)b * Pn * Xn, Pn, Xn, Cn);
        cudaEventRecord(evG1[b], 0);
    }
    for (int b = 0; b < Bn; b++) {
        cudaStreamWaitEvent(s2, evG1[b], 0);
        softmax_spmm_kernel<<<Pn, 256, 0, s2>>>(
            S, qh, ql, kh, kl, v, feat, out, b * Pn);
    }
    cudaEventRecord(evJoin, s2);
    cudaStreamWaitEvent(0, evJoin, 0);
}

// round 17
// speedup vs baseline: 1.0210x; 1.0210x over previous
#include <cuda_runtime.h>
#include <cuda_fp16.h>
#include <cstdint>
#include <cstddef>

typedef __half f16;
#define DI __device__ __forceinline__

constexpr int Bn = 4, Pn = 1024, Xn = 8192, Cn = 1024;
// symmetric fold: q *= S32, k *= c * S32  ->  q.k carries 1/32 = 1/sqrt(C)
#define S32 0.1767766952966369f

// ---------------- scratch (device globals, no allocation) ----------------
__device__ f16   g_qh[(size_t)Bn * Pn * Cn];
__device__ f16   g_ql[(size_t)Bn * Pn * Cn];   // only read by repair
__device__ f16   g_kh[(size_t)Bn * Xn * Cn];
__device__ f16   g_kl[(size_t)Bn * Xn * Cn];   // only read by repair
__device__ f16   g_v [(size_t)Bn * Xn * Cn];
__device__ float g_S [(size_t)Bn * Pn * Xn];   // scores fp32

// ---------------- PTX helpers ----------------
DI void cp_async16(uint32_t saddr, const void* gptr) {
    asm volatile("cp.async.cg.shared.global [%0], [%1], 16;\n" :: "r"(saddr), "l"(gptr));
}
DI void cp_commit() { asm volatile("cp.async.commit_group;\n"); }
template <int N> DI void cp_wait() { asm volatile("cp.async.wait_group %0;\n" :: "n"(N)); }

DI void ldsm4(uint32_t addr, uint32_t& r0, uint32_t& r1, uint32_t& r2, uint32_t& r3) {
    asm volatile("ldmatrix.sync.aligned.m8n8.x4.shared.b16 {%0,%1,%2,%3}, [%4];\n"
                 : "=r"(r0), "=r"(r1), "=r"(r2), "=r"(r3) : "r"(addr));
}
DI void mma16816(float c[4], const uint32_t a[4], const uint32_t b[2]) {
    asm volatile(
        "mma.sync.aligned.m16n8k16.row.col.f32.f16.f16.f32 "
        "{%0,%1,%2,%3}, {%4,%5,%6,%7}, {%8,%9}, {%0,%1,%2,%3};\n"
        : "+f"(c[0]), "+f"(c[1]), "+f"(c[2]), "+f"(c[3])
        : "r"(a[0]), "r"(a[1]), "r"(a[2]), "r"(a[3]), "r"(b[0]), "r"(b[1]));
}

// Swizzled byte offset inside a (rows x 64) f16 tile with 128B rows (SW128 XOR).
DI uint32_t swz(int r, int c8) { return (uint32_t)(r * 128 + ((c8 ^ (r & 7)) << 4)); }

// ---------------- LayerNorm -> f16 (optionally hi/lo split), C = 1024 ----------------
__global__ void __launch_bounds__(256) ln_kernel(
    const float* __restrict__ src, f16* __restrict__ dst_h, f16* __restrict__ dst_l,
    const float* __restrict__ gamma, const float* __restrict__ beta,
    const float* __restrict__ cscale, float sconst)
{
    const int row = blockIdx.x;
    const int t = threadIdx.x;
    const float4* s4 = reinterpret_cast<const float4*>(src) + (size_t)row * 256;
    float4 x = s4[t];
    float sum = x.x + x.y + x.z + x.w;
    float sq  = fmaf(x.x, x.x, fmaf(x.y, x.y, fmaf(x.z, x.z, x.w * x.w)));
#pragma unroll
    for (int o = 16; o; o >>= 1) {
        sum += __shfl_xor_sync(0xffffffffu, sum, o);
        sq  += __shfl_xor_sync(0xffffffffu, sq,  o);
    }
    __shared__ float s_sum[8], s_sq[8];
    if ((t & 31) == 0) { s_sum[t >> 5] = sum; s_sq[t >> 5] = sq; }
    __syncthreads();
    sum = 0.f; sq = 0.f;
#pragma unroll
    for (int i = 0; i < 8; i++) { sum += s_sum[i]; sq += s_sq[i]; }
    const float mu  = sum * (1.f / 1024.f);
    const float var = sq * (1.f / 1024.f) - mu * mu;
    const float rs  = rsqrtf(var + 1e-5f);
    const float sc  = (cscale ? __ldg(cscale + row) : 1.f) * sconst;

    const float4 g = reinterpret_cast<const float4*>(gamma)[t];
    const float4 b = reinterpret_cast<const float4*>(beta)[t];
    float y[4];
    y[0] = ((x.x - mu) * rs * g.x + b.x) * sc;
    y[1] = ((x.y - mu) * rs * g.y + b.y) * sc;
    y[2] = ((x.z - mu) * rs * g.z + b.z) * sc;
    y[3] = ((x.w - mu) * rs * g.w + b.w) * sc;

    __half2 h01 = __floats2half2_rn(y[0], y[1]);
    __half2 h23 = __floats2half2_rn(y[2], y[3]);
    uint2 pk;
    pk.x = *reinterpret_cast<uint32_t*>(&h01);
    pk.y = *reinterpret_cast<uint32_t*>(&h23);
    reinterpret_cast<uint2*>(dst_h + (size_t)row * 1024)[t] = pk;

    if (dst_l) {
        float l0 = y[0] - __half2float(__low2half(h01));
        float l1 = y[1] - __half2float(__high2half(h01));
        float l2 = y[2] - __half2float(__low2half(h23));
        float l3 = y[3] - __half2float(__high2half(h23));
        __half2 l01 = __floats2half2_rn(l0, l1);
        __half2 l23 = __floats2half2_rn(l2, l3);
        uint2 pl;
        pl.x = *reinterpret_cast<uint32_t*>(&l01);
        pl.y = *reinterpret_cast<uint32_t*>(&l23);
        reinterpret_cast<uint2*>(dst_l + (size_t)row * 1024)[t] = pl;
    }
}

// ---------------- tiled f16 GEMM (GEMM1 only): 128x256 CTA tile, fp32 out ----------
// Batched over blockIdx.z. 512 threads, 4x4 warp grid (each warp 32 rows x 64 cols).
template <int STAGES>
__global__ void __launch_bounds__(512, 1) gemm_kernel(
    const f16* __restrict__ A0, const f16* __restrict__ B0,
    float* __restrict__ Co, int M, int N, int K)
{
    extern __shared__ __align__(1024) char smem_raw[];
    constexpr int A_SZ = 16384;                       // 128 x 64 f16
    constexpr int B_SZ = 32768;                       // 256 x 64 f16
    constexpr int SS   = A_SZ + B_SZ;                 // 48KB / stage
    const int tid = threadIdx.x, lane = tid & 31, warp = tid >> 5;
    const int wm = warp & 3, wn = warp >> 2;          // 4 x 4 warp grid
    const int bN = blockIdx.x, bM = blockIdx.y, bz = blockIdx.z;

    const f16* Ap = A0 + (size_t)bz * M * K + (size_t)bM * 128 * K;
    const f16* Bp = B0 + (size_t)bz * N * K + (size_t)bN * 256 * K;

    const uint32_t sb = (uint32_t)__cvta_generic_to_shared(smem_raw);
    const int KT = K >> 6;

    auto fill = [&](int t) {
        const int k0 = t * 64;
        const uint32_t base = sb + (uint32_t)(t % STAGES) * SS;
#pragma unroll
        for (int i = 0; i < 2; i++) {                 // A: 1024 chunks / 512 thr
            int idx = tid + i * 512; int r = idx >> 3, c8 = idx & 7;
            cp_async16(base + swz(r, c8), Ap + (size_t)r * K + k0 + c8 * 8);
        }
#pragma unroll
        for (int i = 0; i < 4; i++) {                 // B: 2048 chunks / 512 thr
            int idx = tid + i * 512; int r = idx >> 3, c8 = idx & 7;
            cp_async16(base + A_SZ + swz(r, c8), Bp + (size_t)r * K + k0 + c8 * 8);
        }
        cp_commit();
    };

    float acc[2][8][4];
#pragma unroll
    for (int mt = 0; mt < 2; mt++)
#pragma unroll
        for (int nt = 0; nt < 8; nt++)
#pragma unroll
            for (int i = 0; i < 4; i++) acc[mt][nt][i] = 0.f;

#pragma unroll
    for (int t = 0; t < STAGES - 1; t++) fill(t);

    for (int kt = 0; kt < KT; kt++) {
        cp_wait<STAGES - 2>();
        __syncthreads();
        { const int t = kt + STAGES - 1; if (t < KT) fill(t); else cp_commit(); }

        const uint32_t base = sb + (uint32_t)(kt % STAGES) * SS;
        const uint32_t sA = base;
        const uint32_t sB = base + A_SZ;
#pragma unroll
        for (int kk = 0; kk < 4; kk++) {
            uint32_t bh[8][2];
#pragma unroll
            for (int np = 0; np < 4; np++) {
                int r = wn * 64 + np * 16 + ((lane >> 4) << 3) + (lane & 7);
                int c8 = kk * 2 + ((lane >> 3) & 1);
                ldsm4(sB + swz(r, c8), bh[2 * np][0], bh[2 * np][1],
                                        bh[2 * np + 1][0], bh[2 * np + 1][1]);
            }
            uint32_t ah[2][4];
#pragma unroll
            for (int mt = 0; mt < 2; mt++) {
                int r = wm * 32 + mt * 16 + (lane & 15);
                int c8 = kk * 2 + (lane >> 4);
                ldsm4(sA + swz(r, c8), ah[mt][0], ah[mt][1], ah[mt][2], ah[mt][3]);
            }
#pragma unroll
            for (int mt = 0; mt < 2; mt++)
#pragma unroll
                for (int nt = 0; nt < 8; nt++)
                    mma16816(acc[mt][nt], ah[mt], bh[nt]);
        }
    }

    const int row0 = bM * 128 + wm * 32;
    const int col0 = bN * 256 + wn * 64;
    const int tr = lane >> 2, tc = (lane & 3) << 1;
    float* C0 = Co + (size_t)bz * M * N;
#pragma unroll
    for (int mt = 0; mt < 2; mt++)
#pragma unroll
        for (int nt = 0; nt < 8; nt++) {
            int p = row0 + mt * 16 + tr, x = col0 + nt * 8 + tc;
            *reinterpret_cast<float2*>(C0 + (size_t)p * N + x) =
                make_float2(acc[mt][nt][0], acc[mt][nt][1]);
            *reinterpret_cast<float2*>(C0 + (size_t)(p + 8) * N + x) =
                make_float2(acc[mt][nt][2], acc[mt][nt][3]);
        }
}

// ---------------- fused softmax + repair + sparse SpMM + residual ----------------
DI float blockMax(float v, float* red) {
#pragma unroll
    for (int o = 16; o; o >>= 1) v = fmaxf(v, __shfl_xor_sync(0xffffffffu, v, o));
    __syncthreads();
    if ((threadIdx.x & 31) == 0) red[threadIdx.x >> 5] = v;
    __syncthreads();
    float r = red[0];
#pragma unroll
    for (int i = 1; i < 8; i++) r = fmaxf(r, red[i]);
    return r;
}
DI float blockSum(float v, float* red) {
#pragma unroll
    for (int o = 16; o; o >>= 1) v += __shfl_xor_sync(0xffffffffu, v, o);
    __syncthreads();
    if ((threadIdx.x & 31) == 0) red[threadIdx.x >> 5] = v;
    __syncthreads();
    float r = 0.f;
#pragma unroll
    for (int i = 0; i < 8; i++) r += red[i];
    return r;
}

constexpr int FCAP = 1024;

__global__ void __launch_bounds__(256) softmax_spmm_kernel(
    const float* __restrict__ S,
    const f16* __restrict__ qh, const f16* __restrict__ ql,
    const f16* __restrict__ kh, const f16* __restrict__ kl,
    const f16* __restrict__ V, const float* __restrict__ feat,
    float* __restrict__ out)
{
    __shared__ float red[8];
    __shared__ float q_s[1024];
    __shared__ int   nf;
    __shared__ int   fx[FCAP];
    __shared__ float fsn[FCAP];
    __shared__ int   sidx[1024];
    __shared__ float sval[1024];
    __shared__ int   wtot[8], wbase[8], s_total;

    const int row = blockIdx.x;                // global row: b*Pn + p
    const int bz  = row >> 10;                 // Pn = 1024
    const int t = threadIdx.x;
    const int lane = t & 31, warp = t >> 5;

    // preload exact q row (qh+ql) to smem
    {
        const uint2 ph = reinterpret_cast<const uint2*>(qh + (size_t)row * 1024)[t];
        const uint2 pl = reinterpret_cast<const uint2*>(ql + (size_t)row * 1024)[t];
        __half2 h0 = *reinterpret_cast<const __half2*>(&ph.x);
        __half2 h1 = *reinterpret_cast<const __half2*>(&ph.y);
        __half2 l0 = *reinterpret_cast<const __half2*>(&pl.x);
        __half2 l1 = *reinterpret_cast<const __half2*>(&pl.y);
        q_s[4 * t + 0] = __low2float(h0)  + __low2float(l0);
        q_s[4 * t + 1] = __high2float(h0) + __high2float(l0);
        q_s[4 * t + 2] = __low2float(h1)  + __low2float(l1);
        q_s[4 * t + 3] = __high2float(h1) + __high2float(l1);
    }
    if (t == 0) nf = 0;

    // load fp32 scores: 8 x float4 = 32 values per thread
    const float4* s4 = reinterpret_cast<const float4*>(S + (size_t)row * Xn);
    float v[8][4];
    float m = -1e30f;
#pragma unroll
    for (int i = 0; i < 8; i++) {
        float4 vv = s4[t + i * 256];
        v[i][0] = vv.x; v[i][1] = vv.y; v[i][2] = vv.z; v[i][3] = vv.w;
        m = fmaxf(m, fmaxf(fmaxf(vv.x, vv.y), fmaxf(vv.z, vv.w)));
    }
    m = blockMax(m, red);                      // also fences q_s / nf writes

    // single exp pass: v becomes e = exp(s - m)
    float z = 0.f;
#pragma unroll
    for (int i = 0; i < 8; i++)
#pragma unroll
        for (int j = 0; j < 4; j++) { v[i][j] = __expf(v[i][j] - m); z += v[i][j]; }
    z = blockSum(z, red);

    // flag entries within +-2e-3 (log domain) of the approximate threshold
    const float ethr1 = 0.0005f * z;
    const float lo = ethr1 * 0.998002f;        // exp(-2e-3)
    const float hi = ethr1 * 1.002002f;        // exp(+2e-3)
#pragma unroll
    for (int i = 0; i < 8; i++)
#pragma unroll
        for (int j = 0; j < 4; j++) {
            if (v[i][j] > lo && v[i][j] < hi) {
                int sl = atomicAdd(&nf, 1);
                if (sl < FCAP) fx[sl] = 4 * (t + i * 256) + j;
            }
        }
    __syncthreads();
    const int nfc = min(nf, FCAP);

    // exact fp32 recompute of flagged scores: one warp per entry
    for (int e = warp; e < nfc; e += 8) {
        const int x = fx[e];
        const uint2* khp = reinterpret_cast<const uint2*>(kh + ((size_t)bz * Xn + x) * 1024);
        const uint2* klp = reinterpret_cast<const uint2*>(kl + ((size_t)bz * Xn + x) * 1024);
        float sum = 0.f;
#pragma unroll
        for (int jj = 0; jj < 8; jj++) {
            const int c4 = lane + jj * 32;
            const uint2 ph = khp[c4];
            const uint2 pl = klp[c4];
            __half2 h0 = *reinterpret_cast<const __half2*>(&ph.x);
            __half2 h1 = *reinterpret_cast<const __half2*>(&ph.y);
            __half2 l0 = *reinterpret_cast<const __half2*>(&pl.x);
            __half2 l1 = *reinterpret_cast<const __half2*>(&pl.y);
            sum = fmaf(q_s[4 * c4 + 0], __low2float(h0)  + __low2float(l0),  sum);
            sum = fmaf(q_s[4 * c4 + 1], __high2float(h0) + __high2float(l0), sum);
            sum = fmaf(q_s[4 * c4 + 2], __low2float(h1)  + __low2float(l1),  sum);
            sum = fmaf(q_s[4 * c4 + 3], __high2float(h1) + __high2float(l1), sum);
        }
#pragma unroll
        for (int o = 16; o; o >>= 1) sum += __shfl_xor_sync(0xffffffffu, sum, o);
        if (lane == 0) fsn[e] = __expf(sum - m);   // exact exp value
    }
    __syncthreads();

    // patch my registers with exact exp values
    for (int e = 0; e < nfc; e++) {
        const int x = fx[e];
        const int q4 = x >> 2;
        if ((q4 & 255) == t) v[q4 >> 8][x & 3] = fsn[e];
    }

    // rebuild Z and threshold from patched values (deterministic full reduction)
    float z_p = 0.f;
#pragma unroll
    for (int i = 0; i < 8; i++)
#pragma unroll
        for (int j = 0; j < 4; j++) z_p += v[i][j];
    z_p = blockSum(z_p, red);
    const float ethr = 0.0005f * z_p;

    float z2 = 0.f;
#pragma unroll
    for (int i = 0; i < 8; i++)
#pragma unroll
        for (int j = 0; j < 4; j++)
            if (v[i][j] >= ethr) z2 += v[i][j];
    z2 = blockSum(z2, red);
    const float inv = 1.f / z2;

    // ---- sparse SpMM: out = feat + inv * sum_{survivors} e_x * V[x, :] ----
    const f16* vb = V + (size_t)bz * Xn * 1024;
    float a0 = 0.f, a1 = 0.f, a2 = 0.f, a3 = 0.f;

    for (int i = 0; i < 8; i++) {
        // survivor mask among my 4 entries of this chunk
        int msk = 0;
#pragma unroll
        for (int j = 0; j < 4; j++) if (v[i][j] >= ethr) msk |= (1 << j);
        int cnt = __popc((unsigned)msk);

        // deterministic compaction: warp inclusive scan + block scan of warp totals
        unsigned inc = (unsigned)cnt;
#pragma unroll
        for (int o = 1; o < 32; o <<= 1) {
            unsigned xx = __shfl_up_sync(0xffffffffu, inc, o);
            if (lane >= o) inc += xx;
        }
        if (lane == 31) wtot[warp] = (int)inc;
        __syncthreads();
        if (t == 0) {
            int s = 0;
#pragma unroll
            for (int w = 0; w < 8; w++) { wbase[w] = s; s += wtot[w]; }
            s_total = s;
        }
        __syncthreads();
        int pos = wbase[warp] + (int)inc - cnt;
#pragma unroll
        for (int j = 0; j < 4; j++) {
            if (msk & (1 << j)) {
                sidx[pos] = 4 * (t + i * 256) + j;
                sval[pos] = v[i][j];
                pos++;
            }
        }
        __syncthreads();
        const int sc = s_total;

        // accumulate survivors: coalesced 2KB gathers of V rows (4-way unrolled for MLP)
        int e = 0;
        for (; e + 4 <= sc; e += 4) {
            const int   x0 = sidx[e],   x1 = sidx[e+1], x2 = sidx[e+2], x3 = sidx[e+3];
            const float w0 = sval[e],   w1 = sval[e+1], w2 = sval[e+2], w3 = sval[e+3];
            const uint2 p0 = *reinterpret_cast<const uint2*>(vb + (size_t)x0 * 1024 + 4 * t);
            const uint2 p1 = *reinterpret_cast<const uint2*>(vb + (size_t)x1 * 1024 + 4 * t);
            const uint2 p2 = *reinterpret_cast<const uint2*>(vb + (size_t)x2 * 1024 + 4 * t);
            const uint2 p3 = *reinterpret_cast<const uint2*>(vb + (size_t)x3 * 1024 + 4 * t);
            float2 f0a = __half22float2(*reinterpret_cast<const __half2*>(&p0.x));
            float2 f0b = __half22float2(*reinterpret_cast<const __half2*>(&p0.y));
            float2 f1a = __half22float2(*reinterpret_cast<const __half2*>(&p1.x));
            float2 f1b = __half22float2(*reinterpret_cast<const __half2*>(&p1.y));
            float2 f2a = __half22float2(*reinterpret_cast<const __half2*>(&p2.x));
            float2 f2b = __half22float2(*reinterpret_cast<const __half2*>(&p2.y));
            float2 f3a = __half22float2(*reinterpret_cast<const __half2*>(&p3.x));
            float2 f3b = __half22float2(*reinterpret_cast<const __half2*>(&p3.y));
            a0 = fmaf(w0, f0a.x, a0); a1 = fmaf(w0, f0a.y, a1);
            a2 = fmaf(w0, f0b.x, a2); a3 = fmaf(w0, f0b.y, a3);
            a0 = fmaf(w1, f1a.x, a0); a1 = fmaf(w1, f1a.y, a1);
            a2 = fmaf(w1, f1b.x, a2); a3 = fmaf(w1, f1b.y, a3);
            a0 = fmaf(w2, f2a.x, a0); a1 = fmaf(w2, f2a.y, a1);
            a2 = fmaf(w2, f2b.x, a2); a3 = fmaf(w2, f2b.y, a3);
            a0 = fmaf(w3, f3a.x, a0); a1 = fmaf(w3, f3a.y, a1);
            a2 = fmaf(w3, f3b.x, a2); a3 = fmaf(w3, f3b.y, a3);
        }
        for (; e < sc; e++) {
            const int x = sidx[e];
            const float w = sval[e];
            const uint2 pv = *reinterpret_cast<const uint2*>(vb + (size_t)x * 1024 + 4 * t);
            float2 f0 = __half22float2(*reinterpret_cast<const __half2*>(&pv.x));
            float2 f1 = __half22float2(*reinterpret_cast<const __half2*>(&pv.y));
            a0 = fmaf(w, f0.x, a0); a1 = fmaf(w, f0.y, a1);
            a2 = fmaf(w, f1.x, a2); a3 = fmaf(w, f1.y, a3);
        }
        __syncthreads();   // protect sidx/sval/wtot for next chunk
    }

    const float4 fr = *reinterpret_cast<const float4*>(feat + (size_t)row * 1024 + 4 * t);
    float4 o4;
    o4.x = fr.x + inv * a0;
    o4.y = fr.y + inv * a1;
    o4.z = fr.z + inv * a2;
    o4.w = fr.w + inv * a3;
    *reinterpret_cast<float4*>(out + (size_t)row * 1024 + 4 * t) = o4;
}

// ---------------- launch (R13 topology: ln_v forked; serial GEMM1 -> fused) --------
extern "C" void kernel_launch(void* const* d_in, const int* in_sizes, int n_in,
                              void* d_out, int out_size)
{
    const float* feat  = (const float*)d_in[0];
    const float* mem_k = (const float*)d_in[1];
    const float* mem_v = (const float*)d_in[2];
    const float* mem_c = (const float*)d_in[3];
    // d_in[4] = mem_attn (unused by reference)
    const float* gq = (const float*)d_in[5];
    const float* bq = (const float*)d_in[6];
    const float* gk = (const float*)d_in[7];
    const float* bk = (const float*)d_in[8];
    const float* gv = (const float*)d_in[9];
    const float* bv = (const float*)d_in[10];
    float* out = (float*)d_out;

    f16 *qh, *ql, *kh, *kl, *v;
    float* S;
    cudaGetSymbolAddress((void**)&qh, g_qh);
    cudaGetSymbolAddress((void**)&ql, g_ql);
    cudaGetSymbolAddress((void**)&kh, g_kh);
    cudaGetSymbolAddress((void**)&kl, g_kl);
    cudaGetSymbolAddress((void**)&v,  g_v);
    cudaGetSymbolAddress((void**)&S,  g_S);

    // side stream + events, created once on the first (non-capturing) call
    static cudaStream_t s2 = nullptr;
    static cudaEvent_t evFork = nullptr, evJoin = nullptr;
    if (!s2) {
        cudaStreamCreateWithFlags(&s2, cudaStreamNonBlocking);
        cudaEventCreateWithFlags(&evFork, cudaEventDisableTiming);
        cudaEventCreateWithFlags(&evJoin, cudaEventDisableTiming);
    }

    // smem: 3 stages x 48KB = 147456 -> 1 CTA/SM at 512 threads
    const int SM = 3 * (16384 + 32768);
    cudaFuncSetAttribute(gemm_kernel<3>, cudaFuncAttributeMaxDynamicSharedMemorySize, SM);

    // fork: V-path (ln_v) on the side stream — needed only by the fused kernel
    cudaEventRecord(evFork, 0);
    cudaStreamWaitEvent(s2, evFork, 0);
    ln_kernel<<<Bn * Xn, 256, 0, s2>>>(mem_v, v, nullptr, gv, bv, nullptr, 1.f);
    cudaEventRecord(evJoin, s2);

    // main path: LN for q and k
    ln_kernel<<<Bn * Pn, 256>>>(feat,  qh, ql, gq, bq, nullptr, S32);
    ln_kernel<<<Bn * Xn, 256>>>(mem_k, kh, kl, gk, bk, mem_c,   S32);

    // S~ = qh @ kh^T  (single fp16 pass, fp32 scores; repaired in fused kernel)
    gemm_kernel<3><<<dim3(Xn / 256, Pn / 128, Bn), 512, SM>>>(
        qh, kh, S, Pn, Xn, Cn);

    // join: fused kernel reads v from the side stream
    cudaStreamWaitEvent(0, evJoin, 0);

    // fused: softmax + threshold repair + sparse SpMM + residual -> out
    softmax_spmm_kernel<<<Bn * Pn, 256>>>(S, qh, ql, kh, kl, v, feat, out);
}